// round 11
// baseline (speedup 1.0000x reference)
#include <cuda_runtime.h>
#include <cuda_bf16.h>
#include <cstdint>
#include <math.h>

#define EMB     1024
#define HEADS   16
#define HEAD_D  128
#define NB      2
#define SEQ     2048
#define OUTD    (HEADS * HEAD_D)   // 2048
#define M_TOTAL (NB * SEQ)         // 4096
#define PK      EMB

// ---------------- scratch ------------------------------------------------------
__device__ __nv_bfloat16 g_Q[(size_t)NB * HEADS * SEQ * HEAD_D];
__device__ __nv_bfloat16 g_K[(size_t)NB * HEADS * SEQ * HEAD_D];
__device__ __nv_bfloat16 g_V[(size_t)NB * HEADS * SEQ * HEAD_D];
__device__ __nv_bfloat16 g_Xb[(size_t)3 * M_TOTAL * PK];
__device__ __nv_bfloat16 g_Wb[(size_t)3 * OUTD * PK];
__device__ unsigned      g_mbits[SEQ * (SEQ / 32)];

__device__ __forceinline__ void cp16(void* dst, const void* src) {
    unsigned d = (unsigned)__cvta_generic_to_shared(dst);
    asm volatile("cp.async.cg.shared.global [%0], [%1], 16;\n" :: "r"(d), "l"(src));
}
#define CP_COMMIT() asm volatile("cp.async.commit_group;\n" ::: "memory")
#define CP_WAIT(k)  asm volatile("cp.async.wait_group %0;\n" :: "n"(k) : "memory")

__device__ __forceinline__ void ldsm_x4(unsigned* r, unsigned addr) {
    asm volatile("ldmatrix.sync.aligned.m8n8.x4.shared.b16 {%0,%1,%2,%3}, [%4];"
        : "=r"(r[0]), "=r"(r[1]), "=r"(r[2]), "=r"(r[3]) : "r"(addr));
}
__device__ __forceinline__ void ldsm_x4t(unsigned* r, unsigned addr) {
    asm volatile("ldmatrix.sync.aligned.m8n8.x4.trans.shared.b16 {%0,%1,%2,%3}, [%4];"
        : "=r"(r[0]), "=r"(r[1]), "=r"(r[2]), "=r"(r[3]) : "r"(addr));
}
__device__ __forceinline__ void mma16816(float* c, const unsigned* a,
                                         unsigned b0, unsigned b1) {
    asm volatile(
        "mma.sync.aligned.m16n8k16.row.col.f32.bf16.bf16.f32 "
        "{%0,%1,%2,%3}, {%4,%5,%6,%7}, {%8,%9}, {%0,%1,%2,%3};"
        : "+f"(c[0]), "+f"(c[1]), "+f"(c[2]), "+f"(c[3])
        : "r"(a[0]), "r"(a[1]), "r"(a[2]), "r"(a[3]), "r"(b0), "r"(b1));
}
__device__ __forceinline__ unsigned packbf(float lo, float hi) {
    unsigned d;
    asm("cvt.rn.bf16x2.f32 %0, %1, %2;" : "=r"(d) : "f"(hi), "f"(lo));
    return d;
}

// ---------------- helpers ------------------------------------------------------
__global__ void pack_mask_kernel(const int* __restrict__ mask, unsigned* __restrict__ bits)
{
    const int e = blockIdx.x * 256 + threadIdx.x;
    const unsigned b = __ballot_sync(0xffffffffu, mask[e] != 0);
    if ((threadIdx.x & 31) == 0) bits[e >> 5] = b;
}

__global__ void cvt_all_kernel(
    const float* __restrict__ p0, const float* __restrict__ p1,
    const float* __restrict__ p2, const float* __restrict__ p3,
    const float* __restrict__ p4, const float* __restrict__ p5,
    __nv_bfloat16* __restrict__ q0, __nv_bfloat16* __restrict__ q1,
    __nv_bfloat16* __restrict__ q2, __nv_bfloat16* __restrict__ q3,
    __nv_bfloat16* __restrict__ q4, __nv_bfloat16* __restrict__ q5)
{
    const int a = blockIdx.y;
    const float* in  = (a == 0) ? p0 : (a == 1) ? p1 : (a == 2) ? p2
                     : (a == 3) ? p3 : (a == 4) ? p4 : p5;
    __nv_bfloat16* out = (a == 0) ? q0 : (a == 1) ? q1 : (a == 2) ? q2
                       : (a == 3) ? q3 : (a == 4) ? q4 : q5;
    const int n4 = (a < 3) ? (M_TOTAL * PK / 4) : (OUTD * PK / 4);
    for (int i = blockIdx.x * 256 + threadIdx.x; i < n4; i += gridDim.x * 256) {
        const float4 v = *(const float4*)(in + (size_t)i * 4);
        __nv_bfloat16* o = out + (size_t)i * 4;
        *(__nv_bfloat162*)(o)     = __nv_bfloat162(__float2bfloat16(v.x), __float2bfloat16(v.y));
        *(__nv_bfloat162*)(o + 2) = __nv_bfloat162(__float2bfloat16(v.z), __float2bfloat16(v.w));
    }
}

// ---------------- projection: raw mma.sync (unchanged from R9) ------------------
#define PR_AS   72
#define PR_STGA (128 * PR_AS)
#define PR_STG  (2 * PR_STGA)
#define PR_NCH  (PK / 64)
#define PR_SMEM (2 * PR_STG * 2 > 128 * 132 * 4 ? 2 * PR_STG * 2 : 128 * 132 * 4)

__global__ __launch_bounds__(256, 2) void proj_kernel(
    const __nv_bfloat16* __restrict__ X0, const __nv_bfloat16* __restrict__ X1,
    const __nv_bfloat16* __restrict__ X2,
    const __nv_bfloat16* __restrict__ W0, const __nv_bfloat16* __restrict__ W1,
    const __nv_bfloat16* __restrict__ W2,
    const float* __restrict__ b0, const float* __restrict__ b1,
    const float* __restrict__ b2,
    __nv_bfloat16* __restrict__ o0, __nv_bfloat16* __restrict__ o1,
    __nv_bfloat16* __restrict__ o2)
{
    const int z = blockIdx.z;
    const __nv_bfloat16* X = (z == 0) ? X0 : (z == 1) ? X1 : X2;
    const __nv_bfloat16* W = (z == 0) ? W0 : (z == 1) ? W1 : W2;
    const float*      bias = (z == 0) ? b0 : (z == 1) ? b1 : b2;
    __nv_bfloat16*     out = (z == 0) ? o0 : (z == 1) ? o1 : o2;

    extern __shared__ char smraw[];
    __nv_bfloat16* sm16 = (__nv_bfloat16*)smraw;
    float* Cs = (float*)smraw;
    const unsigned sbase = (unsigned)__cvta_generic_to_shared(smraw);

    const int tid    = threadIdx.x;
    const int warp   = tid >> 5;
    const int lane   = tid & 31;
    const int warp_m = warp >> 1;
    const int warp_n = warp & 1;
    const int rowBase = blockIdx.y * 128;
    const int colBase = blockIdx.x * 128;

    const __nv_bfloat16* Ag = X + (size_t)rowBase * PK;
    const __nv_bfloat16* Bg = W + (size_t)colBase * PK;

    float c[2][8][4];
    #pragma unroll
    for (int i = 0; i < 2; i++)
        #pragma unroll
        for (int j = 0; j < 8; j++)
            #pragma unroll
            for (int q = 0; q < 4; q++) c[i][j][q] = 0.f;

    auto fill = [&](int s, int ck) {
        __nv_bfloat16* As = sm16 + s * PR_STG;
        __nv_bfloat16* Bs = As + PR_STGA;
        const __nv_bfloat16* Ac = Ag + ck * 64;
        const __nv_bfloat16* Bc = Bg + ck * 64;
        #pragma unroll
        for (int it = 0; it < 4; it++) {
            const int f = tid + 256 * it;
            const int row = f >> 3;
            const int ch  = f & 7;
            cp16(As + row * PR_AS + ch * 8, Ac + (size_t)row * PK + ch * 8);
            cp16(Bs + row * PR_AS + ch * 8, Bc + (size_t)row * PK + ch * 8);
        }
    };

    fill(0, 0); CP_COMMIT();
    fill(1, 1); CP_COMMIT();

    const int arow_off = lane & 15;
    const int acol_off = (lane >> 4) << 3;
    const int krow_off = (lane & 7) + ((lane >> 4) << 3);
    const int kcol_off = lane & 8;

    for (int ck = 0; ck < PR_NCH; ck++) {
        const int s = ck & 1;
        CP_WAIT(1);
        __syncthreads();

        const unsigned abase = sbase + (unsigned)(s * PR_STG) * 2;
        const unsigned bbase = abase + (unsigned)PR_STGA * 2;

        #pragma unroll
        for (int k16 = 0; k16 < 4; k16++) {
            unsigned a0[4], a1[4];
            ldsm_x4(a0, abase + (unsigned)(((warp_m * 32 + arow_off) * PR_AS
                                            + k16 * 16 + acol_off) * 2));
            ldsm_x4(a1, abase + (unsigned)(((warp_m * 32 + 16 + arow_off) * PR_AS
                                            + k16 * 16 + acol_off) * 2));
            #pragma unroll
            for (int nb = 0; nb < 4; nb++) {
                unsigned b[4];
                ldsm_x4(b, bbase + (unsigned)(((warp_n * 64 + nb * 16 + krow_off) * PR_AS
                                               + k16 * 16 + kcol_off) * 2));
                mma16816(c[0][2 * nb],     a0, b[0], b[1]);
                mma16816(c[0][2 * nb + 1], a0, b[2], b[3]);
                mma16816(c[1][2 * nb],     a1, b[0], b[1]);
                mma16816(c[1][2 * nb + 1], a1, b[2], b[3]);
            }
        }
        __syncthreads();
        if (ck + 2 < PR_NCH) { fill(s, ck + 2); CP_COMMIT(); }
    }

    const int r0  = lane >> 2;
    const int lq2 = (lane & 3) * 2;
    #pragma unroll
    for (int i = 0; i < 2; i++) {
        const int row = warp_m * 32 + i * 16 + r0;
        #pragma unroll
        for (int j = 0; j < 8; j++) {
            const int col = warp_n * 64 + j * 8 + lq2;
            Cs[row * 132 + col]       = c[i][j][0];
            Cs[row * 132 + col + 1]   = c[i][j][1];
            Cs[(row + 8) * 132 + col]     = c[i][j][2];
            Cs[(row + 8) * 132 + col + 1] = c[i][j][3];
        }
    }
    __syncthreads();

    const int h = colBase >> 7;
    #pragma unroll
    for (int it = 0; it < 16; it++) {
        const int f   = tid + 256 * it;
        const int row = f >> 5;
        const int c4  = (f & 31) * 4;
        float4 v = *(const float4*)(Cs + row * 132 + c4);
        const float4 bv = *(const float4*)(bias + colBase + c4);
        v.x = fmaxf(v.x + bv.x, 0.f);
        v.y = fmaxf(v.y + bv.y, 0.f);
        v.z = fmaxf(v.z + bv.z, 0.f);
        v.w = fmaxf(v.w + bv.w, 0.f);
        const int m  = rowBase + row;
        const int nb = m >> 11;
        const int sq = m & 2047;
        __nv_bfloat16* op = out + (((size_t)(nb * HEADS + h)) * SEQ + sq) * HEAD_D + c4;
        *(__nv_bfloat162*)(op)     = __nv_bfloat162(__float2bfloat16(v.x), __float2bfloat16(v.y));
        *(__nv_bfloat162*)(op + 2) = __nv_bfloat162(__float2bfloat16(v.z), __float2bfloat16(v.w));
    }
}

// ---------------- attention: 128 thr, BQ=64, intra-tile MUFU/MMA pipelining -----
#define BQ    64
#define BKV   64
#define QSTR  136          // bf16 row stride: 272B, ldmatrix conflict-free
#define NT    (SEQ / BKV)  // 32
#define OSTR  132
#define ATHR  128

__global__ __launch_bounds__(ATHR, 2) void attn_kernel(
    const __nv_bfloat16* __restrict__ Q, const __nv_bfloat16* __restrict__ K,
    const __nv_bfloat16* __restrict__ V, const unsigned* __restrict__ mbits,
    float* __restrict__ out)
{
    extern __shared__ char smraw[];
    __nv_bfloat16* Qs  = (__nv_bfloat16*)smraw;      // 64 x QSTR
    __nv_bfloat16* KV0 = Qs + BQ * QSTR;             // 2 stages x (K 64xQSTR, V 64xQSTR)
    float*         Os  = (float*)KV0;                // epilogue staging (64 x OSTR)

    const int tid  = threadIdx.x;
    const int warp = tid >> 5;        // 0..3
    const int lane = tid & 31;
    const int nb = blockIdx.z;
    const int h  = blockIdx.y;
    const int qt = blockIdx.x;
    const int q0 = qt * BQ;

    const __nv_bfloat16* Qg = Q + (((size_t)(nb * HEADS + h)) * SEQ + q0) * HEAD_D;
    const __nv_bfloat16* Kg = K + (((size_t)(nb * HEADS + h)) * SEQ) * HEAD_D;
    const __nv_bfloat16* Vg = V + (((size_t)(nb * HEADS + h)) * SEQ) * HEAD_D;

    // async load Q (group 0)
    #pragma unroll
    for (int it = 0; it < 8; it++) {
        const int f = tid + ATHR * it;
        const int row = f >> 4;
        const int c8 = (f & 15) * 8;
        cp16(Qs + row * QSTR + c8, Qg + row * HEAD_D + c8);
    }
    CP_COMMIT();

    // async load K/V stage 0 (group 1)
    {
        __nv_bfloat16* Ks0 = KV0;
        __nv_bfloat16* Vs0 = KV0 + BKV * QSTR;
        #pragma unroll
        for (int it = 0; it < 8; it++) {
            const int f = tid + ATHR * it;
            const int row = f >> 4;
            const int c8 = (f & 15) * 8;
            cp16(Ks0 + row * QSTR + c8, Kg + row * HEAD_D + c8);
            cp16(Vs0 + row * QSTR + c8, Vg + row * HEAD_D + c8);
        }
    }
    CP_COMMIT();

    CP_WAIT(1);
    __syncthreads();

    // persistent Q A-fragments
    const unsigned qbase = (unsigned)__cvta_generic_to_shared(Qs);
    unsigned qa[8][4];
    {
        const int qrow = warp * 16 + (lane & 15);
        const int qco  = (lane >> 4) << 3;
        #pragma unroll
        for (int d8 = 0; d8 < 8; d8++)
            ldsm_x4(qa[d8], qbase + (unsigned)((qrow * QSTR + d8 * 16 + qco) * 2));
    }

    float oacc[16][4];
    #pragma unroll
    for (int j = 0; j < 16; j++) {
        #pragma unroll
        for (int q = 0; q < 4; q++) oacc[j][q] = 0.f;
    }
    float li0 = 0.f;
    float li1 = 0.f;

    const float scale = 0.08838834764831845f;
    const int lq2 = (lane & 3) * 2;
    const int r0  = lane >> 2;
    const unsigned* mrow0 = mbits + (size_t)(q0 + warp * 16 + r0) * (SEQ / 32);
    const unsigned* mrow1 = mrow0 + 8 * (SEQ / 32);

    const int krow_off = (lane & 7) + ((lane >> 4) << 3);
    const int kcol_off = lane & 8;
    const int vrow_off = lane & 15;
    const int vcol_off = (lane >> 4) << 3;

    for (int kt = 0; kt < NT; kt++) {
        const int st = kt & 1;
        __syncthreads();   // all warps done reading stage st^1
        if (kt + 1 < NT) {
            __nv_bfloat16* Kn = KV0 + (st ^ 1) * 2 * BKV * QSTR;
            __nv_bfloat16* Vn = Kn + BKV * QSTR;
            const __nv_bfloat16* Kt = Kg + (size_t)(kt + 1) * BKV * HEAD_D;
            const __nv_bfloat16* Vt = Vg + (size_t)(kt + 1) * BKV * HEAD_D;
            #pragma unroll
            for (int it = 0; it < 8; it++) {
                const int f = tid + ATHR * it;
                const int row = f >> 4;
                const int c8 = (f & 15) * 8;
                cp16(Kn + row * QSTR + c8, Kt + row * HEAD_D + c8);
                cp16(Vn + row * QSTR + c8, Vt + row * HEAD_D + c8);
            }
            CP_COMMIT();
            CP_WAIT(1);
        } else {
            CP_WAIT(0);
        }
        __syncthreads();   // stage st visible

        // mask words for this tile
        const unsigned w00 = mrow0[kt * 2];      // A half, rows r0
        const unsigned w01 = mrow0[kt * 2 + 1];  // B half, rows r0
        const unsigned w10 = mrow1[kt * 2];      // A half, rows r0+8
        const unsigned w11 = mrow1[kt * 2 + 1];  // B half, rows r0+8

        __nv_bfloat16* Ks = KV0 + st * 2 * BKV * QSTR;
        __nv_bfloat16* Vs = Ks + BKV * QSTR;
        const unsigned kbase = (unsigned)__cvta_generic_to_shared(Ks);
        const unsigned vbase = (unsigned)__cvta_generic_to_shared(Vs);

        float sA[4][4], sB[4][4];
        #pragma unroll
        for (int j = 0; j < 4; j++) {
            #pragma unroll
            for (int q = 0; q < 4; q++) { sA[j][q] = 0.f; sB[j][q] = 0.f; }
        }

        // exp of one element (j = 8-col group within half, c = accumulator slot)
        auto expA1 = [&](int j, int c) {
            const int sh = j * 8 + lq2 + (c & 1);
            const unsigned w = (c < 2) ? w00 : w10;
            const float e = ((w >> sh) & 1u) ? __expf(sA[j][c] * scale) : 0.f;
            sA[j][c] = e;
            if (c < 2) li0 += e; else li1 += e;
        };
        auto expB1 = [&](int j, int c) {
            const int sh = j * 8 + lq2 + (c & 1);
            const unsigned w = (c < 2) ? w01 : w11;
            const float e = ((w >> sh) & 1u) ? __expf(sB[j][c] * scale) : 0.f;
            sB[j][c] = e;
            if (c < 2) li0 += e; else li1 += e;
        };

        // ---- phase 1: QK_A (cols 0..31), pure tensor ----
        #pragma unroll
        for (int d8 = 0; d8 < 8; d8++) {
            #pragma unroll
            for (int jp = 0; jp < 2; jp++) {
                unsigned b[4];
                ldsm_x4(b, kbase + (unsigned)(((jp * 16 + krow_off) * QSTR
                                               + d8 * 16 + kcol_off) * 2));
                mma16816(sA[2 * jp],     qa[d8], b[0], b[1]);
                mma16816(sA[2 * jp + 1], qa[d8], b[2], b[3]);
            }
        }

        // ---- phase 2: QK_B (cols 32..63) interleaved with exp_A ----
        #pragma unroll
        for (int d8 = 0; d8 < 8; d8++) {
            {
                unsigned b[4];
                ldsm_x4(b, kbase + (unsigned)(((2 * 16 + krow_off) * QSTR
                                               + d8 * 16 + kcol_off) * 2));
                mma16816(sB[0], qa[d8], b[0], b[1]);
                mma16816(sB[1], qa[d8], b[2], b[3]);
            }
            expA1(d8 >> 2, (d8 & 3));            // elements 0..7: j=0..1
            {
                unsigned b[4];
                ldsm_x4(b, kbase + (unsigned)(((3 * 16 + krow_off) * QSTR
                                               + d8 * 16 + kcol_off) * 2));
                mma16816(sB[2], qa[d8], b[0], b[1]);
                mma16816(sB[3], qa[d8], b[2], b[3]);
            }
            expA1(2 + (d8 >> 2), (d8 & 3));      // elements 8..15: j=2..3
        }

        // ---- phase 3: pack A; PV_A (V rows 0..31) interleaved with exp_B ----
        unsigned paA[8];
        paA[0] = packbf(sA[0][0], sA[0][1]);
        paA[1] = packbf(sA[0][2], sA[0][3]);
        paA[2] = packbf(sA[1][0], sA[1][1]);
        paA[3] = packbf(sA[1][2], sA[1][3]);
        paA[4] = packbf(sA[2][0], sA[2][1]);
        paA[5] = packbf(sA[2][2], sA[2][3]);
        paA[6] = packbf(sA[3][0], sA[3][1]);
        paA[7] = packbf(sA[3][2], sA[3][3]);

        #pragma unroll
        for (int kk = 0; kk < 2; kk++) {
            #pragma unroll
            for (int dp = 0; dp < 8; dp++) {
                unsigned v[4];
                ldsm_x4t(v, vbase + (unsigned)(((kk * 16 + vrow_off) * QSTR
                                                + dp * 16 + vcol_off) * 2));
                mma16816(oacc[2 * dp],     paA + 4 * kk, v[0], v[1]);
                mma16816(oacc[2 * dp + 1], paA + 4 * kk, v[2], v[3]);
                expB1((kk * 8 + dp) >> 2, (kk * 8 + dp) & 3);   // 16 elems of B
            }
        }

        // ---- phase 4: pack B; PV_B (V rows 32..63), pure tensor ----
        unsigned paB[8];
        paB[0] = packbf(sB[0][0], sB[0][1]);
        paB[1] = packbf(sB[0][2], sB[0][3]);
        paB[2] = packbf(sB[1][0], sB[1][1]);
        paB[3] = packbf(sB[1][2], sB[1][3]);
        paB[4] = packbf(sB[2][0], sB[2][1]);
        paB[5] = packbf(sB[2][2], sB[2][3]);
        paB[6] = packbf(sB[3][0], sB[3][1]);
        paB[7] = packbf(sB[3][2], sB[3][3]);

        #pragma unroll
        for (int kk = 0; kk < 2; kk++) {
            #pragma unroll
            for (int dp = 0; dp < 8; dp++) {
                unsigned v[4];
                ldsm_x4t(v, vbase + (unsigned)((((kk + 2) * 16 + vrow_off) * QSTR
                                                + dp * 16 + vcol_off) * 2));
                mma16816(oacc[2 * dp],     paB + 4 * kk, v[0], v[1]);
                mma16816(oacc[2 * dp + 1], paB + 4 * kk, v[2], v[3]);
            }
        }
    }

    __syncthreads();   // all warps done with KV smem before O staging overwrites it

    // reduce row sums across the quad
    li0 += __shfl_xor_sync(0xffffffffu, li0, 1);
    li0 += __shfl_xor_sync(0xffffffffu, li0, 2);
    li1 += __shfl_xor_sync(0xffffffffu, li1, 1);
    li1 += __shfl_xor_sync(0xffffffffu, li1, 2);
    const float inv0 = 1.0f / li0;
    const float inv1 = 1.0f / li1;

    // normalize + stage to smem, coalesced write
    {
        float* o0 = Os + (warp * 16 + r0) * OSTR + lq2;
        float* o1 = o0 + 8 * OSTR;
        #pragma unroll
        for (int dj = 0; dj < 16; dj++) {
            o0[dj * 8 + 0] = oacc[dj][0] * inv0;
            o0[dj * 8 + 1] = oacc[dj][1] * inv0;
            o1[dj * 8 + 0] = oacc[dj][2] * inv1;
            o1[dj * 8 + 1] = oacc[dj][3] * inv1;
        }
    }
    __syncthreads();

    #pragma unroll
    for (int it = 0; it < 16; it++) {
        const int f   = tid + ATHR * it;
        const int row = f >> 5;
        const int c4  = (f & 31) * 4;
        const float4 v = *(const float4*)(Os + row * OSTR + c4);
        const int s = q0 + row;
        *(float4*)(out + ((size_t)nb * SEQ + s) * OUTD + h * HEAD_D + c4) = v;
    }
}

// ---------------- launch --------------------------------------------------------
extern "C" void kernel_launch(void* const* d_in, const int* in_sizes, int n_in,
                              void* d_out, int out_size)
{
    const float* query = (const float*)d_in[0];
    const float* key   = (const float*)d_in[1];
    const float* value = (const float*)d_in[2];
    const int*   mask  = (const int*)d_in[3];
    const float* Wq    = (const float*)d_in[4];
    const float* bq    = (const float*)d_in[5];
    const float* Wk    = (const float*)d_in[6];
    const float* bk    = (const float*)d_in[7];
    const float* Wv    = (const float*)d_in[8];
    const float* bv    = (const float*)d_in[9];
    float* out = (float*)d_out;

    __nv_bfloat16 *qb = 0, *kb = 0, *vb = 0, *xb = 0, *wb = 0;
    unsigned* mb = 0;
    cudaGetSymbolAddress((void**)&qb, g_Q);
    cudaGetSymbolAddress((void**)&kb, g_K);
    cudaGetSymbolAddress((void**)&vb, g_V);
    cudaGetSymbolAddress((void**)&xb, g_Xb);
    cudaGetSymbolAddress((void**)&wb, g_Wb);
    cudaGetSymbolAddress((void**)&mb, g_mbits);

    const size_t XN = (size_t)M_TOTAL * PK;
    const size_t WN = (size_t)OUTD * PK;
    __nv_bfloat16* Xb0 = xb;
    __nv_bfloat16* Xb1 = xb + XN;
    __nv_bfloat16* Xb2 = xb + 2 * XN;
    __nv_bfloat16* Wb0 = wb;
    __nv_bfloat16* Wb1 = wb + WN;
    __nv_bfloat16* Wb2 = wb + 2 * WN;

    dim3 cgrid(512, 6);
    cvt_all_kernel<<<cgrid, 256>>>(query, key, value, Wq, Wk, Wv,
                                   Xb0, Xb1, Xb2, Wb0, Wb1, Wb2);
    pack_mask_kernel<<<(SEQ * SEQ) / 256, 256>>>(mask, mb);

    const int proj_smem = PR_SMEM;
    cudaFuncSetAttribute(proj_kernel, cudaFuncAttributeMaxDynamicSharedMemorySize,
                         proj_smem);
    dim3 pgrid(OUTD / 128, M_TOTAL / 128, 3);
    proj_kernel<<<pgrid, 256, proj_smem>>>(Xb0, Xb1, Xb2, Wb0, Wb1, Wb2,
                                           bq, bk, bv, qb, kb, vb);

    const int attn_smem = (BQ * QSTR + 4 * BKV * QSTR) * 2;   // 87040
    cudaFuncSetAttribute(attn_kernel, cudaFuncAttributeMaxDynamicSharedMemorySize,
                         attn_smem);
    dim3 agrid(SEQ / BQ, HEADS, NB);
    attn_kernel<<<agrid, ATHR, attn_smem>>>(qb, kb, vb, mb, out);
}